// round 3
// baseline (speedup 1.0000x reference)
#include <cuda_runtime.h>
#include <cuda_bf16.h>
#include <cstdint>
#include <cstddef>

// ============================================================
// ExpanderLinear: y = x @ W^T + bias
//   x: [N_TOK, 1024] fp32; W: 1024x1024 dense-scattered from 65536 nnz
// Strategy: dense tf32 GEMM via legacy mma.sync (tcgen05 unavailable at
// the harness's compute_103 PTX target), cp.async double-buffered.
// ============================================================
#define INDIM   1024
#define OUTDIM  1024
#define MAXROWS 50048              // 50000 padded to multiple of 128

#define BM 128
#define BN 128
#define BK 32
#define KTILES (INDIM / BK)        // 32
#define THREADS 256

#define LDS 36                     // padded row stride in floats (conflict-free)
#define A_FLOATS (BM * LDS)        // 4608
#define B_FLOATS (BN * LDS)        // 4608
#define STAGE_FLOATS (A_FLOATS + B_FLOATS)       // 9216
#define SMEM_BYTES (2 * STAGE_FLOATS * 4)        // 73728

__device__ float g_W[OUTDIM * INDIM];            // 4 MB dense weight (tf32 RN)
__device__ float g_X[(size_t)MAXROWS * INDIM];   // tf32 RN, zero-padded x
__device__ int   g_is64;                         // edge_index dtype flag

// ============================================================
// Helpers
// ============================================================
__device__ __forceinline__ float tf32_rn(float x) {
    uint32_t u;
    asm("cvt.rn.tf32.f32 %0, %1;" : "=r"(u) : "f"(x));
    return __uint_as_float(u);
}
__device__ __forceinline__ uint32_t smem_u32(const void* p) {
    uint32_t a;
    asm("{ .reg .u64 t; cvta.to.shared.u64 t, %1; cvt.u32.u64 %0, t; }" : "=r"(a) : "l"(p));
    return a;
}
__device__ __forceinline__ void cp_async16(uint32_t dst, const void* src) {
    asm volatile("cp.async.cg.shared.global [%0], [%1], 16;" :: "r"(dst), "l"(src));
}
#define CP_COMMIT() asm volatile("cp.async.commit_group;" ::: "memory")
#define CP_WAIT0()  asm volatile("cp.async.wait_group 0;" ::: "memory")

__device__ __forceinline__ void mma_tf32(float* d, const float* a, const float* b) {
    asm volatile(
        "mma.sync.aligned.m16n8k8.row.col.f32.tf32.tf32.f32 "
        "{%0,%1,%2,%3}, {%4,%5,%6,%7}, {%8,%9}, {%0,%1,%2,%3};"
        : "+f"(d[0]), "+f"(d[1]), "+f"(d[2]), "+f"(d[3])
        : "r"(__float_as_uint(a[0])), "r"(__float_as_uint(a[1])),
          "r"(__float_as_uint(a[2])), "r"(__float_as_uint(a[3])),
          "r"(__float_as_uint(b[0])), "r"(__float_as_uint(b[1])));
}

// ============================================================
// Prep kernels
// ============================================================
__global__ void detect_kernel(const int* __restrict__ ei) {
    // If edge_index is int64, values < 1024 => every odd 32-bit word is 0.
    __shared__ int allzero;
    if (threadIdx.x == 0) allzero = 1;
    __syncthreads();
    if (ei[threadIdx.x * 2 + 1] != 0) allzero = 0;
    __syncthreads();
    if (threadIdx.x == 0) g_is64 = allzero;
}

__global__ void scatter_kernel(const int* __restrict__ ei,
                               const float* __restrict__ val, int nnz) {
    int i = blockIdx.x * 256 + threadIdx.x;
    if (i >= nnz) return;
    int r, c;
    if (g_is64) {
        const long long* e = (const long long*)ei;
        r = (int)e[i];
        c = (int)e[nnz + i];
    } else {
        r = ei[i];
        c = ei[nnz + i];
    }
    atomicAdd(&g_W[r * INDIM + c], val[i]);
}

__global__ void roundW_kernel() {
    int i = blockIdx.x * 256 + threadIdx.x;   // over float4s
    float4* p = reinterpret_cast<float4*>(g_W);
    float4 v = p[i];
    v.x = tf32_rn(v.x); v.y = tf32_rn(v.y); v.z = tf32_rn(v.z); v.w = tf32_rn(v.w);
    p[i] = v;
}

__global__ void roundX_kernel(const float* __restrict__ x, int valid4, int total4) {
    int i = blockIdx.x * 256 + threadIdx.x;
    if (i >= total4) return;
    float4 v = make_float4(0.f, 0.f, 0.f, 0.f);
    if (i < valid4) v = reinterpret_cast<const float4*>(x)[i];
    v.x = tf32_rn(v.x); v.y = tf32_rn(v.y); v.z = tf32_rn(v.z); v.w = tf32_rn(v.w);
    reinterpret_cast<float4*>(g_X)[i] = v;
}

// ============================================================
// GEMM: out[m, n] = sum_k X[m,k] * W[n,k] + bias[n]
// BM=128 x BN=128 x BK=32, 8 warps in 2(m) x 4(n), warp tile 64x32.
// ============================================================
__global__ void __launch_bounds__(THREADS)
gemm_kernel(const float* __restrict__ bias, float* __restrict__ out, int n_tok) {
    extern __shared__ float smem[];
    uint32_t sbase = smem_u32(smem);

    const int tid  = threadIdx.x;
    const int wid  = tid >> 5;
    const int lane = tid & 31;
    const int g    = lane >> 2;    // group id 0..7
    const int t    = lane & 3;     // thread in group 0..3

    const int n0 = (blockIdx.x & 7) * BN;   // n fastest -> A-tile L2 reuse
    const int m0 = (blockIdx.x >> 3) * BM;

    const int wm = (wid & 1) * 64;          // warp m-offset in tile
    const int wn = (wid >> 1) * 32;         // warp n-offset in tile

    // ---- stage loader: A [128 x 32] + B [128 x 32] fp32, row stride 36 ----
    auto load_stage = [&](int s, int kc) {
        const int k0 = kc * BK;
        uint32_t dstA = sbase + s * STAGE_FLOATS * 4;
        uint32_t dstB = dstA + A_FLOATS * 4;
        #pragma unroll
        for (int it = 0; it < 4; it++) {              // 1024 chunks of 16B (A)
            int ch = tid + it * THREADS;
            int m = ch >> 3, c = ch & 7;
            cp_async16(dstA + m * (LDS * 4) + c * 16,
                       &g_X[(size_t)(m0 + m) * INDIM + k0 + c * 4]);
        }
        #pragma unroll
        for (int it = 0; it < 4; it++) {              // 1024 chunks of 16B (B)
            int ch = tid + it * THREADS;
            int n = ch >> 3, c = ch & 7;
            cp_async16(dstB + n * (LDS * 4) + c * 16,
                       &g_W[(n0 + n) * INDIM + k0 + c * 4]);
        }
        CP_COMMIT();
    };

    float acc[4][4][4];
    #pragma unroll
    for (int i = 0; i < 4; i++)
        #pragma unroll
        for (int j = 0; j < 4; j++)
            #pragma unroll
            for (int r = 0; r < 4; r++) acc[i][j][r] = 0.f;

    load_stage(0, 0);

    for (int kc = 0; kc < KTILES; kc++) {
        CP_WAIT0();
        __syncthreads();            // data(kc) visible; compute(kc-1) done
        if (kc + 1 < KTILES) load_stage((kc + 1) & 1, kc + 1);

        const float* sA = smem + (kc & 1) * STAGE_FLOATS;
        const float* sB = sA + A_FLOATS;

        #pragma unroll
        for (int ks = 0; ks < 4; ks++) {
            const int k0 = ks * 8;
            float a[4][4], b[4][2];
            #pragma unroll
            for (int tm = 0; tm < 4; tm++) {
                const float* p = sA + (wm + tm * 16 + g) * LDS + k0 + t;
                a[tm][0] = p[0];
                a[tm][1] = p[8 * LDS];
                a[tm][2] = p[4];
                a[tm][3] = p[8 * LDS + 4];
            }
            #pragma unroll
            for (int tn = 0; tn < 4; tn++) {
                const float* q = sB + (wn + tn * 8 + g) * LDS + k0 + t;
                b[tn][0] = q[0];
                b[tn][1] = q[4];
            }
            #pragma unroll
            for (int tm = 0; tm < 4; tm++)
                #pragma unroll
                for (int tn = 0; tn < 4; tn++)
                    mma_tf32(acc[tm][tn], a[tm], b[tn]);
        }
    }

    // ---- epilogue: add bias, store (float2 per row-piece) ----
    #pragma unroll
    for (int tn = 0; tn < 4; tn++) {
        const int c = n0 + wn + tn * 8 + 2 * t;
        const float bv0 = bias[c];
        const float bv1 = bias[c + 1];
        #pragma unroll
        for (int tm = 0; tm < 4; tm++) {
            const int r0 = m0 + wm + tm * 16 + g;
            const int r1 = r0 + 8;
            if (r0 < n_tok) {
                float2 v = make_float2(acc[tm][tn][0] + bv0, acc[tm][tn][1] + bv1);
                *reinterpret_cast<float2*>(&out[(size_t)r0 * OUTDIM + c]) = v;
            }
            if (r1 < n_tok) {
                float2 v = make_float2(acc[tm][tn][2] + bv0, acc[tm][tn][3] + bv1);
                *reinterpret_cast<float2*>(&out[(size_t)r1 * OUTDIM + c]) = v;
            }
        }
    }
}

// ============================================================
// Launch
// ============================================================
extern "C" void kernel_launch(void* const* d_in, const int* in_sizes, int n_in,
                              void* d_out, int out_size) {
    const float* x    = (const float*)d_in[0];
    const float* wval = (const float*)d_in[1];
    const float* bias = (const float*)d_in[2];
    const int*   ei   = (const int*)d_in[3];   // int32 or int64 (detected)

    int n_tok = in_sizes[0] / INDIM;           // 50000
    int nnz   = in_sizes[1];                   // 65536
    float* out = (float*)d_out;

    void* wptr = nullptr;
    cudaGetSymbolAddress(&wptr, g_W);

    // 1. detect edge_index dtype, zero W, scatter, round W to tf32 (RN)
    detect_kernel<<<1, 256>>>(ei);
    cudaMemsetAsync(wptr, 0, sizeof(float) * OUTDIM * INDIM, 0);
    scatter_kernel<<<(nnz + 255) / 256, 256>>>(ei, wval, nnz);
    roundW_kernel<<<(OUTDIM * INDIM / 4) / 256, 256>>>();

    // 2. round x to tf32 (RN), zero-pad to tile multiple
    int mtiles = (n_tok + BM - 1) / BM;        // 391
    int total4 = mtiles * BM * (INDIM / 4);
    int valid4 = n_tok * (INDIM / 4);
    roundX_kernel<<<(total4 + 255) / 256, 256>>>(x, valid4, total4);

    // 3. tf32 mma.sync GEMM
    cudaFuncSetAttribute(gemm_kernel, cudaFuncAttributeMaxDynamicSharedMemorySize, SMEM_BYTES);
    gemm_kernel<<<mtiles * (OUTDIM / BN), THREADS, SMEM_BYTES>>>(bias, out, n_tok);
}

// round 4
// speedup vs baseline: 1.1075x; 1.1075x over previous
#include <cuda_runtime.h>
#include <cuda_bf16.h>
#include <cstdint>
#include <cstddef>

// ============================================================
// ExpanderLinear: y = x @ W^T + bias
//   x: [N_TOK, 1024] fp32; W: 1024x1024 dense-scattered from 65536 nnz
// Dense tf32 GEMM via legacy mma.sync (tcgen05 unavailable at the
// harness's compute_103 PTX target), cp.async double-buffered.
// R3: no x pre-round pass (HW tf32 truncation of A), W rounded in
// scatter, prep fused -> 3 launches/call.
// ============================================================
#define INDIM   1024
#define OUTDIM  1024

#define BM 128
#define BN 128
#define BK 32
#define KTILES (INDIM / BK)        // 32
#define THREADS 256

#define LDS 36                     // padded row stride in floats (conflict-free)
#define A_FLOATS (BM * LDS)        // 4608
#define B_FLOATS (BN * LDS)        // 4608
#define STAGE_FLOATS (A_FLOATS + B_FLOATS)       // 9216
#define SMEM_BYTES (2 * STAGE_FLOATS * 4)        // 73728

__device__ float g_W[OUTDIM * INDIM];            // 4 MB dense weight (tf32 RN values)
__device__ int   g_is64;                         // edge_index dtype flag

// ============================================================
// Helpers
// ============================================================
__device__ __forceinline__ float tf32_rn(float x) {
    uint32_t u;
    asm("cvt.rn.tf32.f32 %0, %1;" : "=r"(u) : "f"(x));
    return __uint_as_float(u);
}
__device__ __forceinline__ uint32_t smem_u32(const void* p) {
    uint32_t a;
    asm("{ .reg .u64 t; cvta.to.shared.u64 t, %1; cvt.u32.u64 %0, t; }" : "=r"(a) : "l"(p));
    return a;
}
__device__ __forceinline__ void cp_async16(uint32_t dst, const void* src) {
    asm volatile("cp.async.cg.shared.global [%0], [%1], 16;" :: "r"(dst), "l"(src));
}
// zero-fill variant: reads sz bytes (0 or 16), zero-fills the rest
__device__ __forceinline__ void cp_async16z(uint32_t dst, const void* src, unsigned sz) {
    asm volatile("cp.async.cg.shared.global [%0], [%1], 16, %2;" :: "r"(dst), "l"(src), "r"(sz));
}
#define CP_COMMIT() asm volatile("cp.async.commit_group;" ::: "memory")
#define CP_WAIT0()  asm volatile("cp.async.wait_group 0;" ::: "memory")

__device__ __forceinline__ void mma_tf32(float* d, const float* a, const float* b) {
    asm volatile(
        "mma.sync.aligned.m16n8k8.row.col.f32.tf32.tf32.f32 "
        "{%0,%1,%2,%3}, {%4,%5,%6,%7}, {%8,%9}, {%0,%1,%2,%3};"
        : "+f"(d[0]), "+f"(d[1]), "+f"(d[2]), "+f"(d[3])
        : "r"(__float_as_uint(a[0])), "r"(__float_as_uint(a[1])),
          "r"(__float_as_uint(a[2])), "r"(__float_as_uint(a[3])),
          "r"(__float_as_uint(b[0])), "r"(__float_as_uint(b[1])));
}

// ============================================================
// Prep: zero W (whole grid) + detect edge_index dtype (block 0)
// grid = 1024 x 256 threads, one float4 per thread
// ============================================================
__global__ void prep_kernel(const int* __restrict__ ei) {
    int i = blockIdx.x * 256 + threadIdx.x;      // 262144 float4s
    reinterpret_cast<float4*>(g_W)[i] = make_float4(0.f, 0.f, 0.f, 0.f);
    if (blockIdx.x == 0) {
        // If edge_index is int64, values < 1024 => every odd 32-bit word is 0.
        __shared__ int allzero;
        if (threadIdx.x == 0) allzero = 1;
        __syncthreads();
        if (ei[threadIdx.x * 2 + 1] != 0) allzero = 0;
        __syncthreads();
        if (threadIdx.x == 0) g_is64 = allzero;
    }
}

__global__ void scatter_kernel(const int* __restrict__ ei,
                               const float* __restrict__ val, int nnz) {
    int i = blockIdx.x * 256 + threadIdx.x;
    if (i >= nnz) return;
    int r, c;
    if (g_is64) {
        const long long* e = (const long long*)ei;
        r = (int)e[i];
        c = (int)e[nnz + i];
    } else {
        r = ei[i];
        c = ei[nnz + i];
    }
    atomicAdd(&g_W[r * INDIM + c], tf32_rn(val[i]));
}

// ============================================================
// GEMM: out[m, n] = sum_k X[m,k] * W[n,k] + bias[n]
// BM=128 x BN=128 x BK=32, 8 warps in 2(m) x 4(n), warp tile 64x32.
// A loaded straight from x with zero-fill for padded rows.
// ============================================================
__global__ void __launch_bounds__(THREADS)
gemm_kernel(const float* __restrict__ x, const float* __restrict__ bias,
            float* __restrict__ out, int n_tok) {
    extern __shared__ float smem[];
    uint32_t sbase = smem_u32(smem);

    const int tid  = threadIdx.x;
    const int wid  = tid >> 5;
    const int lane = tid & 31;
    const int g    = lane >> 2;    // group id 0..7
    const int t    = lane & 3;     // thread in group 0..3

    const int n0 = (blockIdx.x & 7) * BN;   // n fastest -> A-tile L2 reuse
    const int m0 = (blockIdx.x >> 3) * BM;

    const int wm = (wid & 1) * 64;          // warp m-offset in tile
    const int wn = (wid >> 1) * 32;         // warp n-offset in tile

    // ---- stage loader: A [128 x 32] from x (zfill OOB rows) + B [128 x 32] from g_W ----
    auto load_stage = [&](int s, int kc) {
        const int k0 = kc * BK;
        uint32_t dstA = sbase + s * STAGE_FLOATS * 4;
        uint32_t dstB = dstA + A_FLOATS * 4;
        #pragma unroll
        for (int it = 0; it < 4; it++) {              // 1024 chunks of 16B (A)
            int ch = tid + it * THREADS;
            int m = ch >> 3, c = ch & 7;
            int row = m0 + m;
            unsigned sz = (row < n_tok) ? 16u : 0u;
            cp_async16z(dstA + m * (LDS * 4) + c * 16,
                        x + (size_t)row * INDIM + k0 + c * 4, sz);
        }
        #pragma unroll
        for (int it = 0; it < 4; it++) {              // 1024 chunks of 16B (B)
            int ch = tid + it * THREADS;
            int n = ch >> 3, c = ch & 7;
            cp_async16(dstB + n * (LDS * 4) + c * 16,
                       &g_W[(n0 + n) * INDIM + k0 + c * 4]);
        }
        CP_COMMIT();
    };

    float acc[4][4][4];
    #pragma unroll
    for (int i = 0; i < 4; i++)
        #pragma unroll
        for (int j = 0; j < 4; j++)
            #pragma unroll
            for (int r = 0; r < 4; r++) acc[i][j][r] = 0.f;

    load_stage(0, 0);

    for (int kc = 0; kc < KTILES; kc++) {
        CP_WAIT0();
        __syncthreads();            // data(kc) visible; compute(kc-1) done
        if (kc + 1 < KTILES) load_stage((kc + 1) & 1, kc + 1);

        const float* sA = smem + (kc & 1) * STAGE_FLOATS;
        const float* sB = sA + A_FLOATS;

        #pragma unroll
        for (int ks = 0; ks < 4; ks++) {
            const int k0 = ks * 8;
            float a[4][4], b[4][2];
            #pragma unroll
            for (int tm = 0; tm < 4; tm++) {
                const float* p = sA + (wm + tm * 16 + g) * LDS + k0 + t;
                a[tm][0] = p[0];
                a[tm][1] = p[8 * LDS];
                a[tm][2] = p[4];
                a[tm][3] = p[8 * LDS + 4];
            }
            #pragma unroll
            for (int tn = 0; tn < 4; tn++) {
                const float* q = sB + (wn + tn * 8 + g) * LDS + k0 + t;
                b[tn][0] = q[0];
                b[tn][1] = q[4];
            }
            #pragma unroll
            for (int tm = 0; tm < 4; tm++)
                #pragma unroll
                for (int tn = 0; tn < 4; tn++)
                    mma_tf32(acc[tm][tn], a[tm], b[tn]);
        }
    }

    // ---- epilogue: add bias, store (float2 per row-piece) ----
    #pragma unroll
    for (int tn = 0; tn < 4; tn++) {
        const int c = n0 + wn + tn * 8 + 2 * t;
        const float bv0 = bias[c];
        const float bv1 = bias[c + 1];
        #pragma unroll
        for (int tm = 0; tm < 4; tm++) {
            const int r0 = m0 + wm + tm * 16 + g;
            const int r1 = r0 + 8;
            if (r0 < n_tok) {
                float2 v = make_float2(acc[tm][tn][0] + bv0, acc[tm][tn][1] + bv1);
                *reinterpret_cast<float2*>(&out[(size_t)r0 * OUTDIM + c]) = v;
            }
            if (r1 < n_tok) {
                float2 v = make_float2(acc[tm][tn][2] + bv0, acc[tm][tn][3] + bv1);
                *reinterpret_cast<float2*>(&out[(size_t)r1 * OUTDIM + c]) = v;
            }
        }
    }
}

// ============================================================
// Launch: exactly 3 kernels per call (prep, scatter, gemm)
// ============================================================
extern "C" void kernel_launch(void* const* d_in, const int* in_sizes, int n_in,
                              void* d_out, int out_size) {
    const float* x    = (const float*)d_in[0];
    const float* wval = (const float*)d_in[1];
    const float* bias = (const float*)d_in[2];
    const int*   ei   = (const int*)d_in[3];   // int32 or int64 (detected)

    int n_tok = in_sizes[0] / INDIM;           // 50000
    int nnz   = in_sizes[1];                   // 65536
    float* out = (float*)d_out;

    // 1. zero W + detect dtype
    prep_kernel<<<(OUTDIM * INDIM / 4) / 256, 256>>>(ei);
    // 2. scatter tf32-rounded values
    scatter_kernel<<<(nnz + 255) / 256, 256>>>(ei, wval, nnz);
    // 3. tf32 mma.sync GEMM
    int mtiles = (n_tok + BM - 1) / BM;        // 391
    cudaFuncSetAttribute(gemm_kernel, cudaFuncAttributeMaxDynamicSharedMemorySize, SMEM_BYTES);
    gemm_kernel<<<mtiles * (OUTDIM / BN), THREADS, SMEM_BYTES>>>(x, bias, out, n_tok);
}